// round 15
// baseline (speedup 1.0000x reference)
#include <cuda_runtime.h>
#include <cuda_fp16.h>
#include <cstdint>

#define NN 100000
#define NE 1600000
#define DIN 128

#define CHUNK 1024
#define NBLK ((NN + CHUNK - 1) / CHUNK)   // 98 scan blocks

// ---------------- scratch (static __device__, no allocation) ----------------
__device__ unsigned long long g_pack[NN];       // (cnt<<32) | fp(w, 2^-25)
__device__ __align__(16) float g_deg[NN];       // deg_inv_sqrt
__device__ int   g_cur[NN];
__device__ int   g_rowstart[NN + 1];
__device__ int   g_bsum[NBLK];
struct __align__(8) Edge { int src; float nrm; };
__device__ Edge  g_edge[NE];
__device__ __align__(16) __half g_h0[(size_t)NN * 128];   // H buffer, even layers
__device__ __align__(16) __half g_h1[(size_t)NN * 128];   // H buffer, odd layers
__device__ __align__(16) __half g_wt0[128 * 128];         // W0^T fp16 [n][k]
__device__ __align__(16) __half g_wt1[128 * 128];         // W1^T
__device__ __align__(16) __half g_wt2[64 * 128];          // W2^T

template <int HSEL>
__device__ __forceinline__ __half* bufH() {
    if constexpr (HSEL == 0) return g_h0;
    else return g_h1;
}

// ---------------- HMMA helpers ----------------
__device__ __forceinline__ uint32_t smem_u32(const void* p) {
    uint32_t a;
    asm("{ .reg .u64 t; cvta.to.shared.u64 t, %1; cvt.u32.u64 %0, t; }" : "=r"(a) : "l"(p));
    return a;
}
__device__ __forceinline__ void ldsm_x4(uint32_t* r, uint32_t addr) {
    asm volatile("ldmatrix.sync.aligned.m8n8.x4.shared.b16 {%0,%1,%2,%3}, [%4];"
                 : "=r"(r[0]), "=r"(r[1]), "=r"(r[2]), "=r"(r[3]) : "r"(addr));
}
__device__ __forceinline__ void ldsm_x2(uint32_t* r, uint32_t addr) {
    asm volatile("ldmatrix.sync.aligned.m8n8.x2.shared.b16 {%0,%1}, [%2];"
                 : "=r"(r[0]), "=r"(r[1]) : "r"(addr));
}
__device__ __forceinline__ void mma16816(float* c, const uint32_t* a, const uint32_t* b) {
    asm volatile("mma.sync.aligned.m16n8k16.row.col.f32.f16.f16.f32 "
                 "{%0,%1,%2,%3}, {%4,%5,%6,%7}, {%8,%9}, {%0,%1,%2,%3};"
                 : "+f"(c[0]), "+f"(c[1]), "+f"(c[2]), "+f"(c[3])
                 : "r"(a[0]), "r"(a[1]), "r"(a[2]), "r"(a[3]), "r"(b[0]), "r"(b[1]));
}

// ---------------- preamble ----------------
__global__ void k_init() {
    int i = blockIdx.x * blockDim.x + threadIdx.x;
    if (i < NN) { g_pack[i] = 0ull; g_cur[i] = 0; }
    if (i == 0) g_rowstart[NN] = NE;   // total is a constant
}

// one packed u64 atomic per edge: hi=count, lo=w in 2^-25 fixed point
__global__ void k_deg_acc(const int* __restrict__ ei, const float* __restrict__ w) {
    int q = blockIdx.x * blockDim.x + threadIdx.x;
    if (q >= NE / 4) return;
    int4   d4 = reinterpret_cast<const int4*>(ei + NE)[q];
    float4 w4 = reinterpret_cast<const float4*>(w)[q];
    atomicAdd(&g_pack[d4.x], (1ull << 32) | (unsigned long long)(uint32_t)(w4.x * 33554432.0f));
    atomicAdd(&g_pack[d4.y], (1ull << 32) | (unsigned long long)(uint32_t)(w4.y * 33554432.0f));
    atomicAdd(&g_pack[d4.z], (1ull << 32) | (unsigned long long)(uint32_t)(w4.z * 33554432.0f));
    atomicAdd(&g_pack[d4.w], (1ull << 32) | (unsigned long long)(uint32_t)(w4.w * 33554432.0f));
}

// scan phase A: per-chunk edge-count sums; unpack deg -> deg_inv_sqrt
__global__ void k_scan_a() {
    __shared__ int red[256];
    int b = blockIdx.x, t = threadIdx.x;
    int base = b * CHUNK;
    int s = 0;
#pragma unroll
    for (int j = 0; j < CHUNK / 256; j++) {
        int i = base + j * 256 + t;
        if (i < NN) {
            unsigned long long p = g_pack[i];
            int cnt = (int)(p >> 32);
            float wsum = (float)(uint32_t)p * (1.0f / 33554432.0f);
            g_deg[i] = rsqrtf(1.0f + wsum);   // self-loop weight 1
            s += cnt;
        }
    }
    red[t] = s;
    __syncthreads();
    for (int off = 128; off > 0; off >>= 1) {
        if (t < off) red[t] += red[t + off];
        __syncthreads();
    }
    if (t == 0) g_bsum[b] = red[0];
}

// scan phase C: block prefix over bsum (computed locally) + chunk scan
__global__ void k_scan_c() {
    __shared__ int sh[256];
    __shared__ int red[256];
    int b = blockIdx.x, t = threadIdx.x;

    // prefix = sum of bsum[0..b)
    red[t] = (t < b && t < NBLK) ? g_bsum[t] : 0;
    __syncthreads();
    for (int off = 128; off > 0; off >>= 1) {
        if (t < off) red[t] += red[t + off];
        __syncthreads();
    }
    int pre = red[0];
    __syncthreads();

    int base = b * CHUNK;
    constexpr int PT = CHUNK / 256;
    int c[PT];
    int s = 0;
#pragma unroll
    for (int j = 0; j < PT; j++) {
        int i = base + t * PT + j;
        c[j] = 0;
        if (i < NN) c[j] = (int)(g_pack[i] >> 32);
        s += c[j];
    }
    sh[t] = s;
    __syncthreads();
    for (int off = 1; off < 256; off <<= 1) {
        int v = (t >= off) ? sh[t - off] : 0;
        __syncthreads();
        sh[t] += v;
        __syncthreads();
    }
    int run = pre + ((t == 0) ? 0 : sh[t - 1]);
#pragma unroll
    for (int j = 0; j < PT; j++) {
        int i = base + t * PT + j;
        if (i < NN) g_rowstart[i] = run;
        run += c[j];
    }
}

__global__ void k_bucket(const int* __restrict__ ei, const float* __restrict__ w,
                         int q_base, int q_end) {
    int q = q_base + blockIdx.x * blockDim.x + threadIdx.x;
    if (q >= q_end) return;
    int4   s4 = reinterpret_cast<const int4*>(ei)[q];
    int4   d4 = reinterpret_cast<const int4*>(ei + NE)[q];
    float4 w4 = reinterpret_cast<const float4*>(w)[q];
#pragma unroll
    for (int j = 0; j < 4; j++) {
        int   s = (j == 0) ? s4.x : (j == 1) ? s4.y : (j == 2) ? s4.z : s4.w;
        int   d = (j == 0) ? d4.x : (j == 1) ? d4.y : (j == 2) ? d4.z : d4.w;
        float v = (j == 0) ? w4.x : (j == 1) ? w4.y : (j == 2) ? w4.z : w4.w;
        int pos = g_rowstart[d] + atomicAdd(&g_cur[d], 1);
        Edge rec; rec.src = s; rec.nrm = g_deg[s] * v * g_deg[d];
        g_edge[pos] = rec;
    }
}

__global__ void k_wconv(const float* __restrict__ W0, const float* __restrict__ W1,
                        const float* __restrict__ W2) {
    int i = blockIdx.x * blockDim.x + threadIdx.x;
    if (i < 128 * 128) {
        int k = i >> 7, n = i & 127;
        g_wt0[n * 128 + k] = __float2half(W0[i]);
        g_wt1[n * 128 + k] = __float2half(W1[i]);
    }
    if (i < 128 * 64) {
        int k = i / 64, n = i % 64;
        g_wt2[n * 128 + k] = __float2half(W2[i]);
    }
}

// ---------------- GEMM0: fp32 X -> H0 (same HMMA core as R14) --------------
__global__ void __launch_bounds__(256, 2) k_gemm0(const float* __restrict__ Xf) {
    constexpr int DOUT = 128, NT = DOUT / 8, ROWB = 272, A_SZ = 128 * ROWB;
    extern __shared__ char smem[];

    const int tid  = threadIdx.x;
    const int wid  = tid >> 5;
    const int lane = tid & 31;
    const int row0 = blockIdx.x * 128;
    __half* H = g_h0;

    for (int u = tid; u < 128 * 16; u += 256) {
        int row = u >> 4, k16 = u & 15;
        int r = row0 + row;
        float4 f0 = make_float4(0.f, 0.f, 0.f, 0.f), f1 = f0;
        if (r < NN) {
            const float4* xr = reinterpret_cast<const float4*>(&Xf[(size_t)r * DIN]);
            f0 = xr[k16 * 2];
            f1 = xr[k16 * 2 + 1];
        }
        __half2 h0 = __floats2half2_rn(f0.x, f0.y);
        __half2 h1 = __floats2half2_rn(f0.z, f0.w);
        __half2 h2 = __floats2half2_rn(f1.x, f1.y);
        __half2 h3 = __floats2half2_rn(f1.z, f1.w);
        uint4 pk;
        pk.x = *reinterpret_cast<uint32_t*>(&h0);
        pk.y = *reinterpret_cast<uint32_t*>(&h1);
        pk.z = *reinterpret_cast<uint32_t*>(&h2);
        pk.w = *reinterpret_cast<uint32_t*>(&h3);
        *reinterpret_cast<uint4*>(smem + row * ROWB + k16 * 16) = pk;
    }
    for (int u = tid; u < DOUT * 16; u += 256) {
        int row = u >> 4, k16 = u & 15;
        uint4 pk = reinterpret_cast<const uint4*>(&g_wt0[(size_t)row * 128])[k16];
        *reinterpret_cast<uint4*>(smem + A_SZ + row * ROWB + k16 * 16) = pk;
    }
    __syncthreads();

    uint32_t sbA = smem_u32(smem);
    uint32_t sbB = sbA + A_SZ;
    int m_idx = lane >> 3;
    uint32_t a_base = sbA + (uint32_t)(wid * 16 + (m_idx & 1) * 8 + (lane & 7)) * ROWB
                          + (uint32_t)((m_idx >> 1) * 8) * 2;
    uint32_t b_rowoff = (uint32_t)(lane & 7) * ROWB + (uint32_t)(((lane >> 3) & 1) * 8) * 2;

    float acc[NT][4];
#pragma unroll
    for (int nt = 0; nt < NT; nt++)
#pragma unroll
        for (int j = 0; j < 4; j++) acc[nt][j] = 0.f;

#pragma unroll
    for (int kk = 0; kk < 8; kk++) {
        uint32_t a[4];
        ldsm_x4(a, a_base + kk * 32);
#pragma unroll
        for (int nt = 0; nt < NT; nt++) {
            uint32_t b[2];
            ldsm_x2(b, sbB + b_rowoff + (uint32_t)(nt * 8) * ROWB + kk * 32);
            mma16816(acc[nt], a, b);
        }
    }

    int grp = lane >> 2, tig = lane & 3;
    int r0 = row0 + wid * 16 + grp;
    int r1 = r0 + 8;
#pragma unroll
    for (int nt = 0; nt < NT; nt++) {
        int col = nt * 8 + tig * 2;
        if (r0 < NN) {
            __half2 h = __floats2half2_rn(acc[nt][0], acc[nt][1]);
            *reinterpret_cast<uint32_t*>(&H[(size_t)r0 * DOUT + col]) = *reinterpret_cast<uint32_t*>(&h);
        }
        if (r1 < NN) {
            __half2 h = __floats2half2_rn(acc[nt][2], acc[nt][3]);
            *reinterpret_cast<uint32_t*>(&H[(size_t)r1 * DOUT + col]) = *reinterpret_cast<uint32_t*>(&h);
        }
    }
}

// ---------------- FUSED: agg(H_in,d128)+bias+relu -> smem A -> HMMA -> H_out ----
// HIN/HOUT select H buffers; WSEL: 1 -> g_wt1 (DOUT=128), 2 -> g_wt2 (DOUT=64)
template <int DOUT, int HIN, int HOUT, int WSEL>
__global__ void __launch_bounds__(256, 2) k_fused(const float* __restrict__ bias) {
    constexpr int NT = DOUT / 8, ROWB = 272, A_SZ = 128 * ROWB;
    extern __shared__ char smem[];

    const int tid  = threadIdx.x;
    const int wid  = tid >> 5;
    const int lane = tid & 31;
    const int row0 = blockIdx.x * 128;
    const __half* Hin  = bufH<HIN>();
    __half*       Hout = bufH<HOUT>();

    // B tile fill first (independent)
    {
        const __half* Wt = (WSEL == 1) ? g_wt1 : g_wt2;
        for (int u = tid; u < DOUT * 16; u += 256) {
            int row = u >> 4, k16 = u & 15;
            uint4 pk = reinterpret_cast<const uint4*>(&Wt[(size_t)row * 128])[k16];
            *reinterpret_cast<uint4*>(smem + A_SZ + row * ROWB + k16 * 16) = pk;
        }
    }

    // Phase 1: aggregate 16 nodes per warp into smem A tile (fp16, bias+relu)
    {
        const uint2* HH = reinterpret_cast<const uint2*>(Hin);
        float4 bb = reinterpret_cast<const float4*>(bias)[lane];
        for (int i = 0; i < 16; i++) {
            int r = wid * 16 + i;          // local row
            int n = row0 + r;              // dst node
            uint2 pk = make_uint2(0, 0);
            if (n < NN) {
                int beg = g_rowstart[n];
                int end = g_rowstart[n + 1];
                float din = g_deg[n];
                float sn  = din * din;
                uint2 hr = HH[(size_t)n * 32 + lane];
                float2 h01 = __half22float2(*reinterpret_cast<__half2*>(&hr.x));
                float2 h23 = __half22float2(*reinterpret_cast<__half2*>(&hr.y));
                float4 acc = make_float4(h01.x * sn, h01.y * sn, h23.x * sn, h23.y * sn);
                int e = beg;
                for (; e + 3 < end; e += 4) {
                    Edge e0 = g_edge[e],     e1 = g_edge[e + 1];
                    Edge e2 = g_edge[e + 2], e3 = g_edge[e + 3];
                    uint2 r0 = HH[(size_t)e0.src * 32 + lane];
                    uint2 r1 = HH[(size_t)e1.src * 32 + lane];
                    uint2 r2 = HH[(size_t)e2.src * 32 + lane];
                    uint2 r3 = HH[(size_t)e3.src * 32 + lane];
                    float2 a01 = __half22float2(*reinterpret_cast<__half2*>(&r0.x));
                    float2 a23 = __half22float2(*reinterpret_cast<__half2*>(&r0.y));
                    float2 b01 = __half22float2(*reinterpret_cast<__half2*>(&r1.x));
                    float2 b23 = __half22float2(*reinterpret_cast<__half2*>(&r1.y));
                    float2 c01 = __half22float2(*reinterpret_cast<__half2*>(&r2.x));
                    float2 c23 = __half22float2(*reinterpret_cast<__half2*>(&r2.y));
                    float2 d01 = __half22float2(*reinterpret_cast<__half2*>(&r3.x));
                    float2 d23 = __half22float2(*reinterpret_cast<__half2*>(&r3.y));
                    acc.x += e0.nrm * a01.x + e1.nrm * b01.x + e2.nrm * c01.x + e3.nrm * d01.x;
                    acc.y += e0.nrm * a01.y + e1.nrm * b01.y + e2.nrm * c01.y + e3.nrm * d01.y;
                    acc.z += e0.nrm * a23.x + e1.nrm * b23.x + e2.nrm * c23.x + e3.nrm * d23.x;
                    acc.w += e0.nrm * a23.y + e1.nrm * b23.y + e2.nrm * c23.y + e3.nrm * d23.y;
                }
                for (; e < end; e++) {
                    Edge e0 = g_edge[e];
                    uint2 rr = HH[(size_t)e0.src * 32 + lane];
                    float2 a01 = __half22float2(*reinterpret_cast<__half2*>(&rr.x));
                    float2 a23 = __half22float2(*reinterpret_cast<__half2*>(&rr.y));
                    acc.x += e0.nrm * a01.x; acc.y += e0.nrm * a01.y;
                    acc.z += e0.nrm * a23.x; acc.w += e0.nrm * a23.y;
                }
                acc.x = fmaxf(acc.x + bb.x, 0.f);
                acc.y = fmaxf(acc.y + bb.y, 0.f);
                acc.z = fmaxf(acc.z + bb.z, 0.f);
                acc.w = fmaxf(acc.w + bb.w, 0.f);
                __half2 o01 = __floats2half2_rn(acc.x, acc.y);
                __half2 o23 = __floats2half2_rn(acc.z, acc.w);
                pk.x = *reinterpret_cast<uint32_t*>(&o01);
                pk.y = *reinterpret_cast<uint32_t*>(&o23);
            }
            *reinterpret_cast<uint2*>(smem + r * ROWB + lane * 8) = pk;
        }
    }
    __syncthreads();

    // Phase 2: HMMA
    uint32_t sbA = smem_u32(smem);
    uint32_t sbB = sbA + A_SZ;
    int m_idx = lane >> 3;
    uint32_t a_base = sbA + (uint32_t)(wid * 16 + (m_idx & 1) * 8 + (lane & 7)) * ROWB
                          + (uint32_t)((m_idx >> 1) * 8) * 2;
    uint32_t b_rowoff = (uint32_t)(lane & 7) * ROWB + (uint32_t)(((lane >> 3) & 1) * 8) * 2;

    float acc[NT][4];
#pragma unroll
    for (int nt = 0; nt < NT; nt++)
#pragma unroll
        for (int j = 0; j < 4; j++) acc[nt][j] = 0.f;

#pragma unroll
    for (int kk = 0; kk < 8; kk++) {
        uint32_t a[4];
        ldsm_x4(a, a_base + kk * 32);
#pragma unroll
        for (int nt = 0; nt < NT; nt++) {
            uint32_t b[2];
            ldsm_x2(b, sbB + b_rowoff + (uint32_t)(nt * 8) * ROWB + kk * 32);
            mma16816(acc[nt], a, b);
        }
    }

    int grp = lane >> 2, tig = lane & 3;
    int r0 = row0 + wid * 16 + grp;
    int r1 = r0 + 8;
#pragma unroll
    for (int nt = 0; nt < NT; nt++) {
        int col = nt * 8 + tig * 2;
        if (r0 < NN) {
            __half2 h = __floats2half2_rn(acc[nt][0], acc[nt][1]);
            *reinterpret_cast<uint32_t*>(&Hout[(size_t)r0 * DOUT + col]) = *reinterpret_cast<uint32_t*>(&h);
        }
        if (r1 < NN) {
            __half2 h = __floats2half2_rn(acc[nt][2], acc[nt][3]);
            *reinterpret_cast<uint32_t*>(&Hout[(size_t)r1 * DOUT + col]) = *reinterpret_cast<uint32_t*>(&h);
        }
    }
}

// ------- final aggregate (d=64, fp32 out, reads H0) -------
__global__ void k_agg_final(const float* __restrict__ bias, float* __restrict__ OUT) {
    int warp = (blockIdx.x * blockDim.x + threadIdx.x) >> 5;
    int lane = threadIdx.x & 31;
    if (warp >= NN) return;

    const __half2* HH = reinterpret_cast<const __half2*>(g_h0);
    int beg = g_rowstart[warp];
    int end = g_rowstart[warp + 1];
    float din = g_deg[warp];
    float sn  = din * din;

    float2 h = __half22float2(HH[(size_t)warp * 32 + lane]);
    float2 acc = make_float2(h.x * sn, h.y * sn);
    int e = beg;
    for (; e + 3 < end; e += 4) {
        Edge e0 = g_edge[e],     e1 = g_edge[e + 1];
        Edge e2 = g_edge[e + 2], e3 = g_edge[e + 3];
        float2 v0 = __half22float2(HH[(size_t)e0.src * 32 + lane]);
        float2 v1 = __half22float2(HH[(size_t)e1.src * 32 + lane]);
        float2 v2 = __half22float2(HH[(size_t)e2.src * 32 + lane]);
        float2 v3 = __half22float2(HH[(size_t)e3.src * 32 + lane]);
        acc.x += e0.nrm * v0.x + e1.nrm * v1.x + e2.nrm * v2.x + e3.nrm * v3.x;
        acc.y += e0.nrm * v0.y + e1.nrm * v1.y + e2.nrm * v2.y + e3.nrm * v3.y;
    }
    for (; e < end; e++) {
        Edge e0 = g_edge[e];
        float2 v = __half22float2(HH[(size_t)e0.src * 32 + lane]);
        acc.x += e0.nrm * v.x; acc.y += e0.nrm * v.y;
    }
    float2 bb = reinterpret_cast<const float2*>(bias)[lane];
    acc.x += bb.x; acc.y += bb.y;
    reinterpret_cast<float2*>(OUT)[(size_t)warp * 32 + lane] = acc;
}

// ---------------- driver ----------------
extern "C" void kernel_launch(void* const* d_in, const int* in_sizes, int n_in,
                              void* d_out, int out_size) {
    const float* x  = (const float*)d_in[0];
    const int*   ei = (const int*)d_in[1];
    const float* ew = (const float*)d_in[2];
    const float* W0 = (const float*)d_in[3];
    const float* b0 = (const float*)d_in[4];
    const float* W1 = (const float*)d_in[5];
    const float* b1 = (const float*)d_in[6];
    const float* W2 = (const float*)d_in[7];
    const float* b2 = (const float*)d_in[8];
    float*       out = (float*)d_out;

    constexpr int SMEM_128 = 128 * 272 + 128 * 272;   // 69632
    constexpr int SMEM_64  = 128 * 272 + 64 * 272;    // 52224

    static cudaStream_t s2 = nullptr;
    static cudaEvent_t  ev[4] = {};
    static bool tried = false, ok = false;
    if (!tried) {
        tried = true;
        ok = (cudaStreamCreateWithFlags(&s2, cudaStreamNonBlocking) == cudaSuccess);
        for (int i = 0; i < 4 && ok; i++)
            ok = (cudaEventCreateWithFlags(&ev[i], cudaEventDisableTiming) == cudaSuccess);
        cudaFuncSetAttribute(k_gemm0, cudaFuncAttributeMaxDynamicSharedMemorySize, SMEM_128);
        cudaFuncSetAttribute(k_fused<128, 0, 1, 1>, cudaFuncAttributeMaxDynamicSharedMemorySize, SMEM_128);
        cudaFuncSetAttribute(k_fused<64,  1, 0, 2>, cudaFuncAttributeMaxDynamicSharedMemorySize, SMEM_64);
    }

    const int T = 256;
    const int deg_blocks  = (NE / 4 + T - 1) / T;
    const int gemm_full   = (NN + 127) / 128;
    const int agg_full    = (NN * 32 + T - 1) / T;
    const int buckq_half  = NE / 8;
    const int buck_blocks = (buckq_half + T - 1) / T;

    if (ok) {
        cudaEventRecord(ev[0], 0);
        cudaStreamWaitEvent(s2, ev[0], 0);

        // ---- s2: preamble + bucket_A ----
        k_init<<<(NN + T - 1) / T, T, 0, s2>>>();
        k_deg_acc<<<deg_blocks, T, 0, s2>>>(ei, ew);
        k_scan_a<<<NBLK, 256, 0, s2>>>();
        k_scan_c<<<NBLK, 256, 0, s2>>>();
        cudaEventRecord(ev[1], s2);                          // scans done
        k_bucket<<<buck_blocks, T, 0, s2>>>(ei, ew, 0, buckq_half);
        cudaEventRecord(ev[2], s2);                          // bucket_A done

        // ---- s0: weights, gemm0 (->H0), bucket_B, join ----
        k_wconv<<<64, 256>>>(W0, W1, W2);
        k_gemm0<<<gemm_full, 256, SMEM_128>>>(x);
        cudaStreamWaitEvent(0, ev[1], 0);
        k_bucket<<<buck_blocks, T>>>(ei, ew, buckq_half, NE / 4);
        cudaStreamWaitEvent(0, ev[2], 0);

        // ---- fused layers + final aggregate ----
        k_fused<128, 0, 1, 1><<<gemm_full, 256, SMEM_128>>>(b0);   // agg0+gemm1: H0->H1
        k_fused<64,  1, 0, 2><<<gemm_full, 256, SMEM_64>>>(b1);    // agg1+gemm2: H1->H0
        k_agg_final<<<agg_full, T>>>(b2, out);                     // agg2: H0->out
    } else {
        // serial fallback
        k_init<<<(NN + T - 1) / T, T>>>();
        k_deg_acc<<<deg_blocks, T>>>(ei, ew);
        k_scan_a<<<NBLK, 256>>>();
        k_scan_c<<<NBLK, 256>>>();
        k_bucket<<<(NE / 4 + T - 1) / T, T>>>(ei, ew, 0, NE / 4);
        k_wconv<<<64, 256>>>(W0, W1, W2);
        k_gemm0<<<gemm_full, 256, SMEM_128>>>(x);
        k_fused<128, 0, 1, 1><<<gemm_full, 256, SMEM_128>>>(b0);
        k_fused<64,  1, 0, 2><<<gemm_full, 256, SMEM_64>>>(b1);
        k_agg_final<<<agg_full, T>>>(b2, out);
    }
}

// round 16
// speedup vs baseline: 1.2912x; 1.2912x over previous
#include <cuda_runtime.h>
#include <cuda_fp16.h>
#include <cstdint>

#define NN 100000
#define NE 1600000
#define DIN 128

#define CHUNK 1024
#define NBLK ((NN + CHUNK - 1) / CHUNK)   // 98 scan blocks

// ---------------- scratch (static __device__, no allocation) ----------------
__device__ unsigned long long g_pack[NN];       // (cnt<<32) | fp(w, 2^-25)
__device__ __align__(16) float g_deg[NN];       // deg_inv_sqrt
__device__ int   g_cur[NN];
__device__ int   g_rowstart[NN + 1];
__device__ int   g_bsum[NBLK];
struct __align__(8) Edge { int src; float nrm; };
__device__ Edge  g_edge[NE];
__device__ __align__(16) __half g_h0[(size_t)NN * 128];   // H buffer, even layers
__device__ __align__(16) __half g_h1[(size_t)NN * 128];   // H buffer, odd layers
__device__ __align__(16) __half g_ah[(size_t)NN * 128];   // activation ping (fp16)
__device__ __align__(16) __half g_bh[(size_t)NN * 128];   // activation pong (fp16)
__device__ __align__(16) __half g_wt0[128 * 128];         // W0^T fp16 [n][k]
__device__ __align__(16) __half g_wt1[128 * 128];         // W1^T
__device__ __align__(16) __half g_wt2[64 * 128];          // W2^T

template <int SEL>
__device__ __forceinline__ const __half* bufh() {
    if constexpr (SEL == 1) return g_ah;
    else return g_bh;
}
template <int HSEL>
__device__ __forceinline__ __half* bufH() {
    if constexpr (HSEL == 0) return g_h0;
    else return g_h1;
}

// ---------------- HMMA helpers ----------------
__device__ __forceinline__ uint32_t smem_u32(const void* p) {
    uint32_t a;
    asm("{ .reg .u64 t; cvta.to.shared.u64 t, %1; cvt.u32.u64 %0, t; }" : "=r"(a) : "l"(p));
    return a;
}
__device__ __forceinline__ void ldsm_x4(uint32_t* r, uint32_t addr) {
    asm volatile("ldmatrix.sync.aligned.m8n8.x4.shared.b16 {%0,%1,%2,%3}, [%4];"
                 : "=r"(r[0]), "=r"(r[1]), "=r"(r[2]), "=r"(r[3]) : "r"(addr));
}
__device__ __forceinline__ void ldsm_x2(uint32_t* r, uint32_t addr) {
    asm volatile("ldmatrix.sync.aligned.m8n8.x2.shared.b16 {%0,%1}, [%2];"
                 : "=r"(r[0]), "=r"(r[1]) : "r"(addr));
}
__device__ __forceinline__ void mma16816(float* c, const uint32_t* a, const uint32_t* b) {
    asm volatile("mma.sync.aligned.m16n8k16.row.col.f32.f16.f16.f32 "
                 "{%0,%1,%2,%3}, {%4,%5,%6,%7}, {%8,%9}, {%0,%1,%2,%3};"
                 : "+f"(c[0]), "+f"(c[1]), "+f"(c[2]), "+f"(c[3])
                 : "r"(a[0]), "r"(a[1]), "r"(a[2]), "r"(a[3]), "r"(b[0]), "r"(b[1]));
}

// ---------------- preamble ----------------
__global__ void k_init() {
    int i = blockIdx.x * blockDim.x + threadIdx.x;
    if (i < NN) { g_pack[i] = 0ull; g_cur[i] = 0; }
    if (i == 0) g_rowstart[NN] = NE;   // total is a constant
}

// one packed u64 atomic per edge: hi=count, lo=w in 2^-25 fixed point
__global__ void k_deg_acc(const int* __restrict__ ei, const float* __restrict__ w) {
    int q = blockIdx.x * blockDim.x + threadIdx.x;
    if (q >= NE / 4) return;
    int4   d4 = reinterpret_cast<const int4*>(ei + NE)[q];
    float4 w4 = reinterpret_cast<const float4*>(w)[q];
    atomicAdd(&g_pack[d4.x], (1ull << 32) | (unsigned long long)(uint32_t)(w4.x * 33554432.0f));
    atomicAdd(&g_pack[d4.y], (1ull << 32) | (unsigned long long)(uint32_t)(w4.y * 33554432.0f));
    atomicAdd(&g_pack[d4.z], (1ull << 32) | (unsigned long long)(uint32_t)(w4.z * 33554432.0f));
    atomicAdd(&g_pack[d4.w], (1ull << 32) | (unsigned long long)(uint32_t)(w4.w * 33554432.0f));
}

// scan phase A: per-chunk edge-count sums; unpack deg -> deg_inv_sqrt
__global__ void k_scan_a() {
    __shared__ int red[256];
    int b = blockIdx.x, t = threadIdx.x;
    int base = b * CHUNK;
    int s = 0;
#pragma unroll
    for (int j = 0; j < CHUNK / 256; j++) {
        int i = base + j * 256 + t;
        if (i < NN) {
            unsigned long long p = g_pack[i];
            int cnt = (int)(p >> 32);
            float wsum = (float)(uint32_t)p * (1.0f / 33554432.0f);
            g_deg[i] = rsqrtf(1.0f + wsum);   // self-loop weight 1
            s += cnt;
        }
    }
    red[t] = s;
    __syncthreads();
    for (int off = 128; off > 0; off >>= 1) {
        if (t < off) red[t] += red[t + off];
        __syncthreads();
    }
    if (t == 0) g_bsum[b] = red[0];
}

// scan phase C: block prefix over bsum (computed locally) + chunk scan
__global__ void k_scan_c() {
    __shared__ int sh[256];
    __shared__ int red[256];
    int b = blockIdx.x, t = threadIdx.x;

    red[t] = (t < b && t < NBLK) ? g_bsum[t] : 0;
    __syncthreads();
    for (int off = 128; off > 0; off >>= 1) {
        if (t < off) red[t] += red[t + off];
        __syncthreads();
    }
    int pre = red[0];
    __syncthreads();

    int base = b * CHUNK;
    constexpr int PT = CHUNK / 256;
    int c[PT];
    int s = 0;
#pragma unroll
    for (int j = 0; j < PT; j++) {
        int i = base + t * PT + j;
        c[j] = 0;
        if (i < NN) c[j] = (int)(g_pack[i] >> 32);
        s += c[j];
    }
    sh[t] = s;
    __syncthreads();
    for (int off = 1; off < 256; off <<= 1) {
        int v = (t >= off) ? sh[t - off] : 0;
        __syncthreads();
        sh[t] += v;
        __syncthreads();
    }
    int run = pre + ((t == 0) ? 0 : sh[t - 1]);
#pragma unroll
    for (int j = 0; j < PT; j++) {
        int i = base + t * PT + j;
        if (i < NN) g_rowstart[i] = run;
        run += c[j];
    }
}

__global__ void k_bucket(const int* __restrict__ ei, const float* __restrict__ w,
                         int q_base, int q_end) {
    int q = q_base + blockIdx.x * blockDim.x + threadIdx.x;
    if (q >= q_end) return;
    int4   s4 = reinterpret_cast<const int4*>(ei)[q];
    int4   d4 = reinterpret_cast<const int4*>(ei + NE)[q];
    float4 w4 = reinterpret_cast<const float4*>(w)[q];
#pragma unroll
    for (int j = 0; j < 4; j++) {
        int   s = (j == 0) ? s4.x : (j == 1) ? s4.y : (j == 2) ? s4.z : s4.w;
        int   d = (j == 0) ? d4.x : (j == 1) ? d4.y : (j == 2) ? d4.z : d4.w;
        float v = (j == 0) ? w4.x : (j == 1) ? w4.y : (j == 2) ? w4.z : w4.w;
        int pos = g_rowstart[d] + atomicAdd(&g_cur[d], 1);
        Edge rec; rec.src = s; rec.nrm = g_deg[s] * v * g_deg[d];
        g_edge[pos] = rec;
    }
}

__global__ void k_wconv(const float* __restrict__ W0, const float* __restrict__ W1,
                        const float* __restrict__ W2) {
    int i = blockIdx.x * blockDim.x + threadIdx.x;
    if (i < 128 * 128) {
        int k = i >> 7, n = i & 127;
        g_wt0[n * 128 + k] = __float2half(W0[i]);
        g_wt1[n * 128 + k] = __float2half(W1[i]);
    }
    if (i < 128 * 64) {
        int k = i / 64, n = i % 64;
        g_wt2[n * 128 + k] = __float2half(W2[i]);
    }
}

// ---------------- HMMA GEMM, writes bufH<HSEL> ----------------
template <int DOUT, int XSEL, int HSEL>
__global__ void __launch_bounds__(256, 2) k_gemm_mma(const float* __restrict__ Xf) {
    constexpr int NT    = DOUT / 8;
    constexpr int ROWB  = 272;
    constexpr int A_SZ  = 128 * ROWB;
    extern __shared__ char smem[];

    const int tid  = threadIdx.x;
    const int wid  = tid >> 5;
    const int lane = tid & 31;
    const int row0 = blockIdx.x * 128;
    __half* H = bufH<HSEL>();

    if (XSEL < 0) {
        for (int u = tid; u < 128 * 16; u += 256) {
            int row = u >> 4, k16 = u & 15;
            int r = row0 + row;
            float4 f0 = make_float4(0.f, 0.f, 0.f, 0.f), f1 = f0;
            if (r < NN) {
                const float4* xr = reinterpret_cast<const float4*>(&Xf[(size_t)r * DIN]);
                f0 = xr[k16 * 2];
                f1 = xr[k16 * 2 + 1];
            }
            __half2 h0 = __floats2half2_rn(f0.x, f0.y);
            __half2 h1 = __floats2half2_rn(f0.z, f0.w);
            __half2 h2 = __floats2half2_rn(f1.x, f1.y);
            __half2 h3 = __floats2half2_rn(f1.z, f1.w);
            uint4 pk;
            pk.x = *reinterpret_cast<uint32_t*>(&h0);
            pk.y = *reinterpret_cast<uint32_t*>(&h1);
            pk.z = *reinterpret_cast<uint32_t*>(&h2);
            pk.w = *reinterpret_cast<uint32_t*>(&h3);
            *reinterpret_cast<uint4*>(smem + row * ROWB + k16 * 16) = pk;
        }
    } else {
        const __half* Xh = bufh<(XSEL < 0) ? 1 : XSEL>();
        for (int u = tid; u < 128 * 16; u += 256) {
            int row = u >> 4, k16 = u & 15;
            int r = row0 + row;
            uint4 pk = make_uint4(0, 0, 0, 0);
            if (r < NN)
                pk = reinterpret_cast<const uint4*>(&Xh[(size_t)r * DIN])[k16];
            *reinterpret_cast<uint4*>(smem + row * ROWB + k16 * 16) = pk;
        }
    }
    {
        const __half* Wt = (DOUT == 64) ? g_wt2 : ((XSEL == 1) ? g_wt1 : g_wt0);
        for (int u = tid; u < DOUT * 16; u += 256) {
            int row = u >> 4, k16 = u & 15;
            uint4 pk = reinterpret_cast<const uint4*>(&Wt[(size_t)row * 128])[k16];
            *reinterpret_cast<uint4*>(smem + A_SZ + row * ROWB + k16 * 16) = pk;
        }
    }
    __syncthreads();

    uint32_t sbA = smem_u32(smem);
    uint32_t sbB = sbA + A_SZ;

    int m_idx = lane >> 3;
    uint32_t a_base = sbA + (uint32_t)(wid * 16 + (m_idx & 1) * 8 + (lane & 7)) * ROWB
                          + (uint32_t)((m_idx >> 1) * 8) * 2;
    uint32_t b_rowoff = (uint32_t)(lane & 7) * ROWB + (uint32_t)(((lane >> 3) & 1) * 8) * 2;

    float acc[NT][4];
#pragma unroll
    for (int nt = 0; nt < NT; nt++)
#pragma unroll
        for (int j = 0; j < 4; j++) acc[nt][j] = 0.f;

#pragma unroll
    for (int kk = 0; kk < 8; kk++) {
        uint32_t a[4];
        ldsm_x4(a, a_base + kk * 32);
#pragma unroll
        for (int nt = 0; nt < NT; nt++) {
            uint32_t b[2];
            ldsm_x2(b, sbB + b_rowoff + (uint32_t)(nt * 8) * ROWB + kk * 32);
            mma16816(acc[nt], a, b);
        }
    }

    int grp = lane >> 2, tig = lane & 3;
    int r0 = row0 + wid * 16 + grp;
    int r1 = r0 + 8;
#pragma unroll
    for (int nt = 0; nt < NT; nt++) {
        int col = nt * 8 + tig * 2;
        if (r0 < NN) {
            __half2 h = __floats2half2_rn(acc[nt][0], acc[nt][1]);
            *reinterpret_cast<uint32_t*>(&H[(size_t)r0 * DOUT + col]) =
                *reinterpret_cast<uint32_t*>(&h);
        }
        if (r1 < NN) {
            __half2 h = __floats2half2_rn(acc[nt][2], acc[nt][3]);
            *reinterpret_cast<uint32_t*>(&H[(size_t)r1 * DOUT + col]) =
                *reinterpret_cast<uint32_t*>(&h);
        }
    }
}

// ------- fused aggregate, 4-wide batched edge loop -------
template <int DOUT, bool RELU, int OSEL, int HSEL>
__global__ void k_agg(const float* __restrict__ bias, float* __restrict__ OUText) {
    int warp = (blockIdx.x * blockDim.x + threadIdx.x) >> 5;
    int lane = threadIdx.x & 31;
    if (warp >= NN) return;

    const __half* H = bufH<HSEL>();
    int beg = g_rowstart[warp];
    int end = g_rowstart[warp + 1];
    float din = g_deg[warp];
    float sn  = din * din;

    if (DOUT == 128) {
        const uint2* HH = reinterpret_cast<const uint2*>(H);
        uint2 hr = HH[(size_t)warp * 32 + lane];
        float2 h01 = __half22float2(*reinterpret_cast<__half2*>(&hr.x));
        float2 h23 = __half22float2(*reinterpret_cast<__half2*>(&hr.y));
        float4 acc = make_float4(h01.x * sn, h01.y * sn, h23.x * sn, h23.y * sn);
        int e = beg;
        for (; e + 3 < end; e += 4) {
            Edge e0 = g_edge[e],     e1 = g_edge[e + 1];
            Edge e2 = g_edge[e + 2], e3 = g_edge[e + 3];
            uint2 r0 = HH[(size_t)e0.src * 32 + lane];
            uint2 r1 = HH[(size_t)e1.src * 32 + lane];
            uint2 r2 = HH[(size_t)e2.src * 32 + lane];
            uint2 r3 = HH[(size_t)e3.src * 32 + lane];
            float2 a01 = __half22float2(*reinterpret_cast<__half2*>(&r0.x));
            float2 a23 = __half22float2(*reinterpret_cast<__half2*>(&r0.y));
            float2 b01 = __half22float2(*reinterpret_cast<__half2*>(&r1.x));
            float2 b23 = __half22float2(*reinterpret_cast<__half2*>(&r1.y));
            float2 c01 = __half22float2(*reinterpret_cast<__half2*>(&r2.x));
            float2 c23 = __half22float2(*reinterpret_cast<__half2*>(&r2.y));
            float2 d01 = __half22float2(*reinterpret_cast<__half2*>(&r3.x));
            float2 d23 = __half22float2(*reinterpret_cast<__half2*>(&r3.y));
            acc.x += e0.nrm * a01.x + e1.nrm * b01.x + e2.nrm * c01.x + e3.nrm * d01.x;
            acc.y += e0.nrm * a01.y + e1.nrm * b01.y + e2.nrm * c01.y + e3.nrm * d01.y;
            acc.z += e0.nrm * a23.x + e1.nrm * b23.x + e2.nrm * c23.x + e3.nrm * d23.x;
            acc.w += e0.nrm * a23.y + e1.nrm * b23.y + e2.nrm * c23.y + e3.nrm * d23.y;
        }
        for (; e < end; e++) {
            Edge e0 = g_edge[e];
            uint2 r0 = HH[(size_t)e0.src * 32 + lane];
            float2 a01 = __half22float2(*reinterpret_cast<__half2*>(&r0.x));
            float2 a23 = __half22float2(*reinterpret_cast<__half2*>(&r0.y));
            acc.x += e0.nrm * a01.x; acc.y += e0.nrm * a01.y;
            acc.z += e0.nrm * a23.x; acc.w += e0.nrm * a23.y;
        }
        float4 bb = reinterpret_cast<const float4*>(bias)[lane];
        acc.x += bb.x; acc.y += bb.y; acc.z += bb.z; acc.w += bb.w;
        if (RELU) {
            acc.x = fmaxf(acc.x, 0.f); acc.y = fmaxf(acc.y, 0.f);
            acc.z = fmaxf(acc.z, 0.f); acc.w = fmaxf(acc.w, 0.f);
        }
        if (OSEL < 0) {
            reinterpret_cast<float4*>(OUText)[(size_t)warp * 32 + lane] = acc;
        } else {
            __half* outh = const_cast<__half*>(bufh<(OSEL < 0) ? 1 : OSEL>());
            __half2 o01 = __floats2half2_rn(acc.x, acc.y);
            __half2 o23 = __floats2half2_rn(acc.z, acc.w);
            uint2 pk;
            pk.x = *reinterpret_cast<uint32_t*>(&o01);
            pk.y = *reinterpret_cast<uint32_t*>(&o23);
            reinterpret_cast<uint2*>(outh)[(size_t)warp * 32 + lane] = pk;
        }
    } else {
        const __half2* HH = reinterpret_cast<const __half2*>(H);
        float2 h = __half22float2(HH[(size_t)warp * 32 + lane]);
        float2 acc = make_float2(h.x * sn, h.y * sn);
        int e = beg;
        for (; e + 3 < end; e += 4) {
            Edge e0 = g_edge[e],     e1 = g_edge[e + 1];
            Edge e2 = g_edge[e + 2], e3 = g_edge[e + 3];
            float2 v0 = __half22float2(HH[(size_t)e0.src * 32 + lane]);
            float2 v1 = __half22float2(HH[(size_t)e1.src * 32 + lane]);
            float2 v2 = __half22float2(HH[(size_t)e2.src * 32 + lane]);
            float2 v3 = __half22float2(HH[(size_t)e3.src * 32 + lane]);
            acc.x += e0.nrm * v0.x + e1.nrm * v1.x + e2.nrm * v2.x + e3.nrm * v3.x;
            acc.y += e0.nrm * v0.y + e1.nrm * v1.y + e2.nrm * v2.y + e3.nrm * v3.y;
        }
        for (; e < end; e++) {
            Edge e0 = g_edge[e];
            float2 v = __half22float2(HH[(size_t)e0.src * 32 + lane]);
            acc.x += e0.nrm * v.x; acc.y += e0.nrm * v.y;
        }
        float2 bb = reinterpret_cast<const float2*>(bias)[lane];
        acc.x += bb.x; acc.y += bb.y;
        if (RELU) { acc.x = fmaxf(acc.x, 0.f); acc.y = fmaxf(acc.y, 0.f); }
        reinterpret_cast<float2*>(OUText)[(size_t)warp * 32 + lane] = acc;
    }
}

// ---------------- driver: serial layers, preamble on s2, bucket split --------
extern "C" void kernel_launch(void* const* d_in, const int* in_sizes, int n_in,
                              void* d_out, int out_size) {
    const float* x  = (const float*)d_in[0];
    const int*   ei = (const int*)d_in[1];
    const float* ew = (const float*)d_in[2];
    const float* W0 = (const float*)d_in[3];
    const float* b0 = (const float*)d_in[4];
    const float* W1 = (const float*)d_in[5];
    const float* b1 = (const float*)d_in[6];
    const float* W2 = (const float*)d_in[7];
    const float* b2 = (const float*)d_in[8];
    float*       out = (float*)d_out;

    constexpr int SMEM_128 = 128 * 272 + 128 * 272;   // 69632
    constexpr int SMEM_64  = 128 * 272 + 64 * 272;    // 52224

    static cudaStream_t s2 = nullptr;
    static cudaEvent_t  ev[4] = {};
    static bool tried = false, ok = false;
    if (!tried) {
        tried = true;
        ok = (cudaStreamCreateWithFlags(&s2, cudaStreamNonBlocking) == cudaSuccess);
        for (int i = 0; i < 4 && ok; i++)
            ok = (cudaEventCreateWithFlags(&ev[i], cudaEventDisableTiming) == cudaSuccess);
        cudaFuncSetAttribute(k_gemm_mma<128, -1, 0>, cudaFuncAttributeMaxDynamicSharedMemorySize, SMEM_128);
        cudaFuncSetAttribute(k_gemm_mma<128,  1, 1>, cudaFuncAttributeMaxDynamicSharedMemorySize, SMEM_128);
        cudaFuncSetAttribute(k_gemm_mma<64,   2, 0>, cudaFuncAttributeMaxDynamicSharedMemorySize, SMEM_64);
    }

    const int T = 256;
    const int deg_blocks  = (NE / 4 + T - 1) / T;
    const int gemm_full   = (NN + 127) / 128;
    const int agg_full    = (NN * 32 + T - 1) / T;
    const int buckq_half  = NE / 8;
    const int buck_blocks = (buckq_half + T - 1) / T;

    if (ok) {
        cudaEventRecord(ev[0], 0);
        cudaStreamWaitEvent(s2, ev[0], 0);

        // ---- s2: preamble + bucket_A ----
        k_init<<<(NN + T - 1) / T, T, 0, s2>>>();
        k_deg_acc<<<deg_blocks, T, 0, s2>>>(ei, ew);
        k_scan_a<<<NBLK, 256, 0, s2>>>();
        k_scan_c<<<NBLK, 256, 0, s2>>>();
        cudaEventRecord(ev[1], s2);                          // scans done
        k_bucket<<<buck_blocks, T, 0, s2>>>(ei, ew, 0, buckq_half);
        cudaEventRecord(ev[2], s2);                          // bucket_A done

        // ---- s0: weights, gemm0 (->H0), bucket_B, join ----
        k_wconv<<<64, 256>>>(W0, W1, W2);
        k_gemm_mma<128, -1, 0><<<gemm_full, 256, SMEM_128>>>(x);
        cudaStreamWaitEvent(0, ev[1], 0);
        k_bucket<<<buck_blocks, T>>>(ei, ew, buckq_half, NE / 4);
        cudaStreamWaitEvent(0, ev[2], 0);

        // ---- serial layers ----
        k_agg<128, true, 1, 0><<<agg_full, T>>>(b0, nullptr);
        k_gemm_mma<128, 1, 1><<<gemm_full, 256, SMEM_128>>>(nullptr);
        k_agg<128, true, 2, 1><<<agg_full, T>>>(b1, nullptr);
        k_gemm_mma<64, 2, 0><<<gemm_full, 256, SMEM_64>>>(nullptr);
        k_agg<64, false, -1, 0><<<agg_full, T>>>(b2, out);
    } else {
        // serial fallback
        k_init<<<(NN + T - 1) / T, T>>>();
        k_deg_acc<<<deg_blocks, T>>>(ei, ew);
        k_scan_a<<<NBLK, 256>>>();
        k_scan_c<<<NBLK, 256>>>();
        k_bucket<<<(NE / 4 + T - 1) / T, T>>>(ei, ew, 0, NE / 4);
        k_wconv<<<64, 256>>>(W0, W1, W2);
        k_gemm_mma<128, -1, 0><<<gemm_full, 256, SMEM_128>>>(x);
        k_agg<128, true, 1, 0><<<agg_full, T>>>(b0, nullptr);
        k_gemm_mma<128, 1, 1><<<gemm_full, 256, SMEM_128>>>(nullptr);
        k_agg<128, true, 2, 1><<<agg_full, T>>>(b1, nullptr);
        k_gemm_mma<64, 2, 0><<<gemm_full, 256, SMEM_64>>>(nullptr);
        k_agg<64, false, -1, 0><<<agg_full, T>>>(b2, out);
    }
}